// round 5
// baseline (speedup 1.0000x reference)
#include <cuda_runtime.h>
#include <cstdint>

#define BATCH 16384
typedef unsigned long long u64;

// ---------------- device scratch (static allocation only) ----------------
__device__ float g_pool1[BATCH * 396];       // pooled conv1 output [b][oc(6)][pp(66)]
__device__ __align__(16) float g_tbl1[480 * 8]; // conv1 lookup: [(ch*5+dy)*32+mask][oc0..5,pad2]
__device__ float g_wc2[2400];                // conv2 w [ci][dy][dx][oc0..15]
__device__ float g_wc3[3072];                // conv3 w [ci*3+dy][oc0..63]
__device__ float g_lfc1T[2048];              // lfc1 transposed [i(64)][j(32)]
__device__ float g_fcwT[256];                // fc_w transposed [i(8)][j(32)]
__device__ float g_watt[1024];               // folded attention weight [k(32)][i(32)]
__device__ float g_batt[32];                 // folded attention bias

__device__ __forceinline__ float relu(float x) { return x > 0.f ? x : 0.f; }
__device__ __forceinline__ void fadd2(u64& d, u64 v) {
    asm("add.rn.f32x2 %0, %0, %1;" : "+l"(d) : "l"(v));
}
__device__ __forceinline__ float2 u2f(u64 v) {
    float2 r; asm("mov.b64 {%0,%1}, %2;" : "=f"(r.x), "=f"(r.y) : "l"(v)); return r;
}

// ---------------- L0: flat-parallel prep (one item per thread) ----------------
__global__ void k_prep(const float* __restrict__ w1, const float* __restrict__ w2,
                       const float* __restrict__ w3, const float* __restrict__ lfc1,
                       const float* __restrict__ fcw, const float* __restrict__ outw,
                       const float* __restrict__ ipw, const float* __restrict__ ipb,
                       const float* __restrict__ outb) {
    int tid = blockIdx.x * blockDim.x + threadIdx.x;
    if (tid < 2880) {
        // conv1 binary lookup table: entry e = (ch*5+dy)*32 + mask, 6 oc each
        int oc = tid % 6; int e = tid / 6;
        int m = e % 32; int cd = e / 32;
        int ch = cd / 5, dy = cd % 5;
        float s = 0.f;
        #pragma unroll
        for (int dx = 0; dx < 5; dx++)
            if ((m >> dx) & 1) s += w1[((oc * 3 + ch) * 5 + dy) * 5 + dx];
        g_tbl1[e * 8 + oc] = s;
    } else if (tid < 5280) {
        int i = tid - 2880;
        int oc = i % 16; int r = i / 16; int dx = r % 5; r /= 5; int dy = r % 5; int ci = r / 5;
        g_wc2[i] = w2[((oc * 6 + ci) * 5 + dy) * 5 + dx];
    } else if (tid < 8352) {
        int i = tid - 5280;
        int o = i % 64; int r = i / 64; int dy = r % 3; int ci = r / 3;
        g_wc3[i] = w3[(o * 16 + ci) * 3 + dy];
    } else if (tid < 10400) {
        int i = tid - 8352;
        int j = i % 32; int k = i / 32; g_lfc1T[i] = lfc1[j * 64 + k];
    } else if (tid < 10656) {
        int i = tid - 10400;
        int j = i % 32; int k = i / 32; g_fcwT[i] = fcw[j * 8 + k];
    } else if (tid < 11680) {
        // W_att[i][j] = sum_k out_w[i,k] * vw[k,j], stored g_watt[j*32+i]
        int i = tid - 10656;
        int ii = i % 32; int j = i / 32;
        float s = 0.f;
        for (int k = 0; k < 32; k++) s += outw[ii * 32 + k] * ipw[(64 + k) * 32 + j];
        g_watt[i] = s;
    } else if (tid < 11712) {
        int i = tid - 11680;
        float s = outb[i];
        for (int k = 0; k < 32; k++) s += outw[i * 32 + k] * ipb[64 + k];
        g_batt[i] = s;
    }
}

// ---------------- L1: board bitmasks + table-lookup conv1 + relu + avgpool ----------------
// 128 threads = 2 samples x 64 threads. Board rows as 16-bit masks; conv via 5-bit LUT.
__global__ __launch_bounds__(128) void k_board_conv1(
    const int* __restrict__ t, const int* __restrict__ ptab,
    const float* __restrict__ b1, float* __restrict__ boardOut, int writeBoard) {
    __shared__ __align__(16) float tbl[480 * 8];   // 15360 B
    __shared__ unsigned srow[2][96];               // [sample][ch*32 + row(26 used)]

    int tid = threadIdx.x;
    int g = tid >> 6;
    int lt = tid & 63;
    int b = blockIdx.x * 2 + g;

    for (int i = tid; i < 960; i += 128)
        ((float4*)tbl)[i] = ((const float4*)g_tbl1)[i];
    srow[g][lt] = 0u;
    if (lt < 32) srow[g][64 + lt] = 0u;
    __syncthreads();

    const int* trow = t + (size_t)b * 232;
    // shared-row coords: board row r -> row r+2, board col c -> bit c+3.
    // frame: bits 2 and 13 on rows 2..22; bottom pad row 23 = bits 2..13.
    if (lt < 21) {
        unsigned m = 0x2004u;
        const int* p = trow + 22 + lt * 10;
        #pragma unroll
        for (int c = 0; c < 10; c++) m |= ((unsigned)p[c]) << (c + 3);
        srow[g][lt + 2] = m;
    } else if (lt < 42) {
        srow[g][32 + (lt - 21) + 2] = 0x2004u;
    } else if (lt < 63) {
        srow[g][64 + (lt - 42) + 2] = 0x2004u;
    } else {
        srow[g][23] = 0x3FFCu; srow[g][32 + 23] = 0x3FFCu; srow[g][64 + 23] = 0x3FFCu;
    }
    __syncthreads();

    // piece cells (channels 1 and 2), single thread per sample
    if (lt == 0) {
        int t1 = trow[1], t2 = trow[2], t3 = trow[3], t4 = trow[4], t8 = trow[8];
        const int* p = ptab + t8 * 64 + t4 * 16;
        int sel[4]; int cnt = 0;
        for (int i = 0; i < 16 && cnt < 4; i++) if (p[i] != 0) sel[cnt++] = i;
        for (int i = 0; i < 16 && cnt < 4; i++) if (p[i] == 0) sel[cnt++] = i;
        for (int s = 0; s < 4; s++) {
            int cy = sel[s] >> 2, cx = sel[s] & 3;
            int x = cx + t1 - 2;
            int y = cy + t2;
            int ny = y + t3;
            if (y >= 0 && ny >= 0 && x >= 0 && x < 10) {
                if (y < 21)  srow[g][32 + y + 2] |= 1u << (x + 3);
                if (ny < 21) srow[g][64 + ny + 2] |= 1u << (x + 3);
            }
        }
    }
    __syncthreads();

    // padded board (B,3,22,12) straight from bits, float4 stores
    if (writeBoard) {
        float4* ob = (float4*)(boardOut + (size_t)b * 792);
        for (int i = lt; i < 198; i += 64) {
            int e = i * 4;
            int ch = e / 264; int rr = (e % 264) / 12; int c0 = e % 12;
            unsigned rw = srow[g][ch * 32 + rr + 2] >> (c0 + 2);
            float4 v;
            v.x = (float)(rw & 1u); v.y = (float)((rw >> 1) & 1u);
            v.z = (float)((rw >> 2) & 1u); v.w = (float)((rw >> 3) & 1u);
            ob[i] = v;
        }
    }

    float bb[6];
    #pragma unroll
    for (int k = 0; k < 6; k++) bb[k] = b1[k];

    const unsigned* rb = srow[g];
    for (int pp = lt; pp < 66; pp += 64) {
        int py = pp / 6, px = pp % 6;
        int x0 = 2 * px, rbase = 2 * py;
        unsigned rws[3][6];
        #pragma unroll
        for (int ch = 0; ch < 3; ch++)
            #pragma unroll
            for (int r = 0; r < 6; r++) rws[ch][r] = rb[ch * 32 + rbase + r];

        u64 aA[4] = {0, 0, 0, 0}, aB[4] = {0, 0, 0, 0}, aC[4] = {0, 0, 0, 0};
        #pragma unroll
        for (int sy = 0; sy < 2; sy++)
            #pragma unroll
            for (int ch = 0; ch < 3; ch++)
                #pragma unroll
                for (int dy = 0; dy < 5; dy++) {
                    unsigned row = rws[ch][sy + dy];
                    int cd = ch * 5 + dy;
                    #pragma unroll
                    for (int sx = 0; sx < 2; sx++) {
                        unsigned m = (row >> (x0 + sx)) & 31u;
                        const float* p = tbl + (((unsigned)cd << 5) + m) * 8;
                        ulonglong2 q = *(const ulonglong2*)p;   // oc0..3
                        u64 v2 = *(const u64*)(p + 4);          // oc4..5
                        int s = sy * 2 + sx;
                        fadd2(aA[s], q.x); fadd2(aB[s], q.y); fadd2(aC[s], v2);
                    }
                }

        float2 A[4], Bv[4], C[4];
        #pragma unroll
        for (int s = 0; s < 4; s++) { A[s] = u2f(aA[s]); Bv[s] = u2f(aB[s]); C[s] = u2f(aC[s]); }
        float* dst = g_pool1 + (size_t)b * 396 + pp;
        dst[0 * 66] = 0.25f * (relu(A[0].x + bb[0]) + relu(A[1].x + bb[0]) + relu(A[2].x + bb[0]) + relu(A[3].x + bb[0]));
        dst[1 * 66] = 0.25f * (relu(A[0].y + bb[1]) + relu(A[1].y + bb[1]) + relu(A[2].y + bb[1]) + relu(A[3].y + bb[1]));
        dst[2 * 66] = 0.25f * (relu(Bv[0].x + bb[2]) + relu(Bv[1].x + bb[2]) + relu(Bv[2].x + bb[2]) + relu(Bv[3].x + bb[2]));
        dst[3 * 66] = 0.25f * (relu(Bv[0].y + bb[3]) + relu(Bv[1].y + bb[3]) + relu(Bv[2].y + bb[3]) + relu(Bv[3].y + bb[3]));
        dst[4 * 66] = 0.25f * (relu(C[0].x + bb[4]) + relu(C[1].x + bb[4]) + relu(C[2].x + bb[4]) + relu(C[3].x + bb[4]));
        dst[5 * 66] = 0.25f * (relu(C[0].y + bb[5]) + relu(C[1].y + bb[5]) + relu(C[2].y + bb[5]) + relu(C[3].y + bb[5]));
    }
}

// ---------------- L2: conv2 + pool + conv3 + fc + folded-attention + xf ----------------
__global__ __launch_bounds__(256) void k_tail(
    const int* __restrict__ t, const float* __restrict__ c2b,
    const float* __restrict__ c3b, const float* __restrict__ l1b,
    const float* __restrict__ fcb, float* __restrict__ out) {
    extern __shared__ float dsm[];
    float* w2s = dsm;                 // 2400
    float* w3s = w2s + 2400;          // 3072
    float* l1s = w3s + 3072;          // 2048
    float* was = l1s + 2048;          // 1024
    float* fws = was + 1024;          // 256
    float* bias = fws + 256;          // 176
    float* wbuf = bias + 176;         // 8 * 736

    int tid = threadIdx.x;
    for (int i = tid; i < 2400; i += 256) w2s[i] = g_wc2[i];
    for (int i = tid; i < 3072; i += 256) w3s[i] = g_wc3[i];
    for (int i = tid; i < 2048; i += 256) l1s[i] = g_lfc1T[i];
    for (int i = tid; i < 1024; i += 256) was[i] = g_watt[i];
    for (int i = tid; i < 256; i += 256) fws[i] = g_fcwT[i];
    for (int i = tid; i < 16; i += 256) bias[i] = c2b[i];
    for (int i = tid; i < 64; i += 256) bias[16 + i] = c3b[i];
    for (int i = tid; i < 32; i += 256) {
        bias[80 + i] = l1b[i];
        bias[112 + i] = fcb[i];
        bias[144 + i] = g_batt[i];
    }
    __syncthreads();

    int w = tid >> 5;
    int lane = tid & 31;
    int b = blockIdx.x * 8 + w;

    float* p1s = wbuf + w * 736;
    float* c2s = p1s + 400;
    float* p2s = c2s + 192;
    float* x64s = p2s + 48;
    float* b2s = x64s + 64;

    for (int i = lane; i < 396; i += 32) p1s[i] = g_pool1[(size_t)b * 396 + i];
    __syncwarp();

    // conv2: lane -> oc = lane&15, x = lane>>4; rows y=0..5 (row 6 dropped by pool)
    {
        int oc = lane & 15;
        int xx = lane >> 4;
        float acc[6];
        float bb = bias[oc];
        #pragma unroll
        for (int y = 0; y < 6; y++) acc[y] = bb;
        for (int ci = 0; ci < 6; ci++) {
            #pragma unroll
            for (int dx = 0; dx < 5; dx++) {
                int col = xx + dx;
                const float* pc = p1s + ci * 66 + col;
                float c[10];
                #pragma unroll
                for (int j = 0; j < 10; j++) c[j] = pc[j * 6];
                const float* wb = w2s + ((ci * 5) * 5 + dx) * 16 + oc;
                #pragma unroll
                for (int dy = 0; dy < 5; dy++) {
                    float wv = wb[dy * 80];
                    acc[0] += wv * c[dy + 0];
                    acc[1] += wv * c[dy + 1];
                    acc[2] += wv * c[dy + 2];
                    acc[3] += wv * c[dy + 3];
                    acc[4] += wv * c[dy + 4];
                    acc[5] += wv * c[dy + 5];
                }
            }
        }
        #pragma unroll
        for (int y = 0; y < 6; y++) c2s[oc * 12 + y * 2 + xx] = relu(acc[y]);
    }
    __syncwarp();

    for (int i = lane; i < 48; i += 32) {
        int base = (i / 3) * 12 + (i % 3) * 4;
        p2s[i] = 0.25f * (c2s[base] + c2s[base + 1] + c2s[base + 2] + c2s[base + 3]);
    }
    __syncwarp();

    {
        float accA = bias[16 + lane];
        float accB = bias[16 + lane + 32];
        #pragma unroll
        for (int k = 0; k < 48; k++) {
            float iv = p2s[k];
            accA += iv * w3s[k * 64 + lane];
            accB += iv * w3s[k * 64 + lane + 32];
        }
        x64s[lane] = relu(accA);
        x64s[lane + 32] = relu(accB);
    }
    __syncwarp();

    {
        float acc = bias[80 + lane];
        #pragma unroll
        for (int i = 0; i < 64; i++) acc += x64s[i] * l1s[i * 32 + lane];
        float v = relu(acc);
        b2s[lane] = v;
        out[(size_t)b * 96 + 64 + lane] = v;
    }
    __syncwarp();

    {
        float acc = bias[144 + lane];
        #pragma unroll
        for (int k = 0; k < 32; k++) acc += b2s[k] * was[k * 32 + lane];
        out[(size_t)b * 96 + 32 + lane] = acc;
    }

    {
        const int* trow = t + (size_t)b * 232;
        float tv = (lane < 8) ? (float)trow[lane] : 0.f;
        float acc = bias[112 + lane];
        #pragma unroll
        for (int i = 0; i < 8; i++) {
            float ti = __shfl_sync(0xffffffffu, tv, i);
            acc += ti * fws[i * 32 + lane];
        }
        out[(size_t)b * 96 + lane] = relu(acc);
    }
}

// ---------------- launch ----------------
extern "C" void kernel_launch(void* const* d_in, const int* in_sizes, int n_in,
                              void* d_out, int out_size) {
    const int* t = (const int*)d_in[0];
    const int* ptab = (const int*)d_in[1];
    const float* w1 = (const float*)d_in[2];
    const float* b1 = (const float*)d_in[3];
    const float* w2 = (const float*)d_in[4];
    const float* b2 = (const float*)d_in[5];
    const float* w3 = (const float*)d_in[6];
    const float* b3 = (const float*)d_in[7];
    const float* lfc1 = (const float*)d_in[8];
    const float* l1b = (const float*)d_in[9];
    const float* fcw = (const float*)d_in[10];
    const float* fcb = (const float*)d_in[11];
    const float* ipw = (const float*)d_in[13];
    const float* ipb = (const float*)d_in[14];
    const float* outw = (const float*)d_in[15];
    const float* outb = (const float*)d_in[16];
    float* out = (float*)d_out;

    int hasBoard = (out_size >= BATCH * (96 + 792)) ? 1 : 0;
    float* boardOut = out + (size_t)BATCH * 96;

    k_prep<<<64, 256>>>(w1, w2, w3, lfc1, fcw, outw, ipw, ipb, outb);
    k_board_conv1<<<BATCH / 2, 128>>>(t, ptab, b1, boardOut, hasBoard);

    static const int kTailSmem = (2400 + 3072 + 2048 + 1024 + 256 + 176 + 8 * 736) * 4;
    cudaFuncSetAttribute(k_tail, cudaFuncAttributeMaxDynamicSharedMemorySize, kTailSmem);
    k_tail<<<BATCH / 8, 256, kTailSmem>>>(t, b2, b3, l1b, fcb, out);
}

// round 6
// speedup vs baseline: 1.0416x; 1.0416x over previous
#include <cuda_runtime.h>
#include <cstdint>

#define BATCH 16384
typedef unsigned long long u64;

__device__ __forceinline__ float relu(float x) { return x > 0.f ? x : 0.f; }
__device__ __forceinline__ u64 dup2(float x) {
    u64 r; asm("mov.b64 %0, {%1,%1};" : "=l"(r) : "f"(x)); return r;
}
__device__ __forceinline__ void fma2(u64& d, u64 a, u64 b) {
    asm("fma.rn.f32x2 %0, %1, %2, %0;" : "+l"(d) : "l"(a), "l"(b));
}
__device__ __forceinline__ float2 u2f(u64 v) {
    float2 r; asm("mov.b64 {%0,%1}, %2;" : "=f"(r.x), "=f"(r.y) : "l"(v)); return r;
}

// shared layout (float offsets):
//   0     sb      4*1248   board planes (26x16 per ch, 3 ch, 4 samples)
//   4992  wc1s    456      conv1 w [ch][dy][dx][oc0..5]
//   5448  w2s     2400     conv2 w [ci][dy][dx][oc0..15]
//   7848  w3s     3072     conv3 w [ci*3+dy][oc0..63]
//   10920 l1s     2048     lfc1^T [k(64)][j(32)]
//   12968 was     1024     folded attention W [k(32)][i(32)]
//   13992 fws     256      fc_w^T [k(8)][j(32)]
//   14248 bias    176      [0:16)c2b [16:80)c3b [80:112)l1b [112:144)fcb [144:176)batt
//   14424 p1      4*396    pooled conv1 output per sample
//   16008 tbuf    4*336    per-warp tail buffers
//   total 17352 floats = 69408 B
// tmp (ow 33-stride 1056 | iv 1024 | ipb 32 | outb 32 = 2144) aliases p1+tbuf (2928)
#define SMEM_FLOATS 17352

__global__ __launch_bounds__(256) void k_fused(
    const int* __restrict__ t, const int* __restrict__ ptab,
    const float* __restrict__ w1, const float* __restrict__ b1,
    const float* __restrict__ w2, const float* __restrict__ c2b,
    const float* __restrict__ w3, const float* __restrict__ c3b,
    const float* __restrict__ lfc1, const float* __restrict__ l1b,
    const float* __restrict__ fcw, const float* __restrict__ fcb,
    const float* __restrict__ ipw, const float* __restrict__ ipb,
    const float* __restrict__ outw, const float* __restrict__ outb,
    float* __restrict__ out, float* __restrict__ boardOut, int writeBoard) {
    extern __shared__ float sm[];
    float* sb   = sm;
    float* wc1s = sm + 4992;
    float* w2s  = sm + 5448;
    float* w3s  = sm + 7848;
    float* l1s  = sm + 10920;
    float* was  = sm + 12968;
    float* fws  = sm + 13992;
    float* bias = sm + 14248;
    float* p1   = sm + 14424;
    float* tbuf = sm + 16008;
    float* ow_s = p1;            // 1056 (stride-33 padded)
    float* iv_s = p1 + 1056;     // 1024
    float* ib_s = p1 + 2080;     // 32
    float* ob_s = p1 + 2112;     // 32

    int tid = threadIdx.x;
    int b0 = blockIdx.x * 4;
    int g = tid >> 6;
    int lt = tid & 63;

    // ---------- step 1: weight loads + re-layout, tmp loads, zero boards ----------
    for (int i = tid; i < 450; i += 256) {
        int oc = i % 6; int r = i / 6; int dx = r % 5; r /= 5; int dy = r % 5; int ch = r / 5;
        wc1s[i] = w1[((oc * 3 + ch) * 5 + dy) * 5 + dx];
    }
    for (int i = tid; i < 2400; i += 256) {
        int oc = i % 16; int r = i / 16; int dx = r % 5; r /= 5; int dy = r % 5; int ci = r / 5;
        w2s[i] = w2[((oc * 6 + ci) * 5 + dy) * 5 + dx];
    }
    for (int i = tid; i < 3072; i += 256) {
        int o = i % 64; int r = i / 64; int dy = r % 3; int ci = r / 3;
        w3s[i] = w3[(o * 16 + ci) * 3 + dy];
    }
    for (int i = tid; i < 2048; i += 256) { int j = i % 32, k = i / 32; l1s[i] = lfc1[j * 64 + k]; }
    for (int i = tid; i < 256; i += 256) { int j = i % 32, k = i / 32; fws[i] = fcw[j * 8 + k]; }
    for (int i = tid; i < 1024; i += 256) {
        ow_s[(i / 32) * 33 + (i % 32)] = outw[i];                 // outw[i][k] row-major
        iv_s[i] = ipw[(64 + (i / 32)) * 32 + (i % 32)];           // vw[k][j]
    }
    for (int i = tid; i < 32; i += 256) {
        ib_s[i] = ipb[64 + i];
        ob_s[i] = outb[i];
        bias[80 + i] = l1b[i];
        bias[112 + i] = fcb[i];
    }
    for (int i = tid; i < 16; i += 256) bias[i] = c2b[i];
    for (int i = tid; i < 64; i += 256) bias[16 + i] = c3b[i];
    for (int i = tid; i < 1248; i += 256) ((float4*)sb)[i] = make_float4(0.f, 0.f, 0.f, 0.f);
    __syncthreads();

    // ---------- step 2: board fill + attention fold ----------
    const int* trow = t + (size_t)(b0 + g) * 232;
    float* S = sb + g * 1248;
    for (int i = lt; i < 210; i += 64) {
        int r = i / 10, c = i % 10;
        S[(r + 2) * 16 + (c + 3)] = (float)trow[22 + i];
    }
    for (int i = lt; i < 168; i += 64) {
        int ch = i / 56, j = i % 56;
        int r, c;
        if (j < 22) { r = j; c = 0; }
        else if (j < 44) { r = j - 22; c = 11; }
        else { r = 21; c = j - 44; }
        S[ch * 416 + (r + 2) * 16 + (c + 2)] = 1.0f;
    }
    if (lt == 0) {
        int t1 = trow[1], t2 = trow[2], t3 = trow[3], t4 = trow[4], t8 = trow[8];
        const int* p = ptab + t8 * 64 + t4 * 16;
        int sel[4]; int cnt = 0;
        for (int i = 0; i < 16 && cnt < 4; i++) if (p[i] != 0) sel[cnt++] = i;
        for (int i = 0; i < 16 && cnt < 4; i++) if (p[i] == 0) sel[cnt++] = i;
        for (int s = 0; s < 4; s++) {
            int cy = sel[s] >> 2, cx = sel[s] & 3;
            int x = cx + t1 - 2;
            int y = cy + t2;
            int ny = y + t3;
            if (y >= 0 && ny >= 0 && x >= 0 && x < 10) {
                if (y < 21)  S[1 * 416 + (y + 2) * 16 + (x + 3)] = 1.0f;
                if (ny < 21) S[2 * 416 + (ny + 2) * 16 + (x + 3)] = 1.0f;
            }
        }
    }
    // W_att[i][j] = sum_k outw[i,k] * vw[k,j]; stored was[j*32+i]
    for (int i = tid; i < 1024; i += 256) {
        int ii = i & 31, j = i >> 5;
        float s = 0.f;
        #pragma unroll
        for (int k = 0; k < 32; k++) s += ow_s[ii * 33 + k] * iv_s[k * 32 + j];
        was[j * 32 + ii] = s;
    }
    if (tid < 32) {
        float s = ob_s[tid];
        #pragma unroll
        for (int k = 0; k < 32; k++) s += ow_s[tid * 33 + k] * ib_s[k];
        bias[144 + tid] = s;
    }
    __syncthreads();

    // ---------- step 3: board write + conv1/relu/pool (flat over 4 samples) ----------
    if (writeBoard) {
        float4* obp = (float4*)(boardOut + (size_t)(b0 + g) * 792);
        for (int i = lt; i < 198; i += 64) {
            int e = i * 4;
            int ch = e / 264, rr = (e % 264) / 12, c0 = e % 12;
            const float* q = S + ch * 416 + (rr + 2) * 16 + (c0 + 2);
            obp[i] = make_float4(q[0], q[1], q[2], q[3]);
        }
    }

    float bb6[6];
    #pragma unroll
    for (int k = 0; k < 6; k++) bb6[k] = b1[k];

    for (int u = tid; u < 264; u += 256) {
        int g2 = u / 66, pp = u % 66;
        const float* P = sb + g2 * 1248;
        int py = pp / 6, px = pp % 6;
        u64 acc00[3] = {0, 0, 0}, acc01[3] = {0, 0, 0};
        u64 acc10[3] = {0, 0, 0}, acc11[3] = {0, 0, 0};
        for (int ch = 0; ch < 3; ch++) {
            const float* plane = P + ch * 416;
            #pragma unroll
            for (int dy = 0; dy < 5; dy++) {
                const u64* r0 = (const u64*)(plane + (2 * py + dy) * 16 + 2 * px);
                const u64* r1 = (const u64*)(plane + (2 * py + dy + 1) * 16 + 2 * px);
                float2 u0 = u2f(r0[0]), u1 = u2f(r0[1]), u2v = u2f(r0[2]);
                float2 v0 = u2f(r1[0]), v1 = u2f(r1[1]), v2v = u2f(r1[2]);
                float ra[6] = {u0.x, u0.y, u1.x, u1.y, u2v.x, u2v.y};
                float rb[6] = {v0.x, v0.y, v1.x, v1.y, v2v.x, v2v.y};
                const u64* wp = (const u64*)(wc1s + (ch * 5 + dy) * 30);
                #pragma unroll
                for (int dx = 0; dx < 5; dx++) {
                    u64 w0 = wp[dx * 3 + 0], w1v = wp[dx * 3 + 1], w2w = wp[dx * 3 + 2];
                    u64 d00 = dup2(ra[dx]), d01 = dup2(ra[dx + 1]);
                    u64 d10 = dup2(rb[dx]), d11 = dup2(rb[dx + 1]);
                    fma2(acc00[0], w0, d00); fma2(acc00[1], w1v, d00); fma2(acc00[2], w2w, d00);
                    fma2(acc01[0], w0, d01); fma2(acc01[1], w1v, d01); fma2(acc01[2], w2w, d01);
                    fma2(acc10[0], w0, d10); fma2(acc10[1], w1v, d10); fma2(acc10[2], w2w, d10);
                    fma2(acc11[0], w0, d11); fma2(acc11[1], w1v, d11); fma2(acc11[2], w2w, d11);
                }
            }
        }
        float* dst = p1 + g2 * 396 + pp;
        #pragma unroll
        for (int k = 0; k < 3; k++) {
            float2 a00 = u2f(acc00[k]), a01 = u2f(acc01[k]);
            float2 a10 = u2f(acc10[k]), a11 = u2f(acc11[k]);
            float bb0 = bb6[2 * k], bb1 = bb6[2 * k + 1];
            dst[(2 * k) * 66] = 0.25f * (relu(a00.x + bb0) + relu(a01.x + bb0) +
                                         relu(a10.x + bb0) + relu(a11.x + bb0));
            dst[(2 * k + 1) * 66] = 0.25f * (relu(a00.y + bb1) + relu(a01.y + bb1) +
                                             relu(a10.y + bb1) + relu(a11.y + bb1));
        }
    }
    __syncthreads();

    // ---------- step 4: tail (warps 0-3, one sample each) ----------
    int w = tid >> 5;
    int lane = tid & 31;
    if (w < 4) {
        int b = b0 + w;
        float* p1s = p1 + w * 396;
        float* c2s = tbuf + w * 336;
        float* p2s = c2s + 192;
        float* x64s = p2s + 48;
        float* b2s = x64s + 64;

        // conv2: lane -> oc = lane&15, x = lane>>4; rows y=0..5 (row 6 dropped by pool)
        {
            int oc = lane & 15;
            int xx = lane >> 4;
            float acc[6];
            float bb = bias[oc];
            #pragma unroll
            for (int y = 0; y < 6; y++) acc[y] = bb;
            for (int ci = 0; ci < 6; ci++) {
                #pragma unroll
                for (int dx = 0; dx < 5; dx++) {
                    const float* pc = p1s + ci * 66 + xx + dx;
                    float c[10];
                    #pragma unroll
                    for (int j = 0; j < 10; j++) c[j] = pc[j * 6];
                    const float* wb = w2s + ((ci * 5) * 5 + dx) * 16 + oc;
                    #pragma unroll
                    for (int dy = 0; dy < 5; dy++) {
                        float wv = wb[dy * 80];
                        acc[0] += wv * c[dy + 0];
                        acc[1] += wv * c[dy + 1];
                        acc[2] += wv * c[dy + 2];
                        acc[3] += wv * c[dy + 3];
                        acc[4] += wv * c[dy + 4];
                        acc[5] += wv * c[dy + 5];
                    }
                }
            }
            #pragma unroll
            for (int y = 0; y < 6; y++) c2s[oc * 12 + y * 2 + xx] = relu(acc[y]);
        }
        __syncwarp();

        for (int i = lane; i < 48; i += 32) {
            int base = (i / 3) * 12 + (i % 3) * 4;
            p2s[i] = 0.25f * (c2s[base] + c2s[base + 1] + c2s[base + 2] + c2s[base + 3]);
        }
        __syncwarp();

        {
            float accA = bias[16 + lane];
            float accB = bias[16 + lane + 32];
            #pragma unroll
            for (int k = 0; k < 48; k++) {
                float iv = p2s[k];
                accA += iv * w3s[k * 64 + lane];
                accB += iv * w3s[k * 64 + lane + 32];
            }
            x64s[lane] = relu(accA);
            x64s[lane + 32] = relu(accB);
        }
        __syncwarp();

        {
            float acc = bias[80 + lane];
            #pragma unroll
            for (int i = 0; i < 64; i++) acc += x64s[i] * l1s[i * 32 + lane];
            float v = relu(acc);
            b2s[lane] = v;
            out[(size_t)b * 96 + 64 + lane] = v;
        }
        __syncwarp();

        {
            float acc = bias[144 + lane];
            #pragma unroll
            for (int k = 0; k < 32; k++) acc += b2s[k] * was[k * 32 + lane];
            out[(size_t)b * 96 + 32 + lane] = acc;
        }

        {
            const int* tr2 = t + (size_t)b * 232;
            float tv = (lane < 8) ? (float)tr2[lane] : 0.f;
            float acc = bias[112 + lane];
            #pragma unroll
            for (int i = 0; i < 8; i++) {
                float ti = __shfl_sync(0xffffffffu, tv, i);
                acc += ti * fws[i * 32 + lane];
            }
            out[(size_t)b * 96 + lane] = relu(acc);
        }
    }
}

// ---------------- launch ----------------
extern "C" void kernel_launch(void* const* d_in, const int* in_sizes, int n_in,
                              void* d_out, int out_size) {
    const int* t = (const int*)d_in[0];
    const int* ptab = (const int*)d_in[1];
    const float* w1 = (const float*)d_in[2];
    const float* b1 = (const float*)d_in[3];
    const float* w2 = (const float*)d_in[4];
    const float* b2 = (const float*)d_in[5];
    const float* w3 = (const float*)d_in[6];
    const float* b3 = (const float*)d_in[7];
    const float* lfc1 = (const float*)d_in[8];
    const float* l1b = (const float*)d_in[9];
    const float* fcw = (const float*)d_in[10];
    const float* fcb = (const float*)d_in[11];
    const float* ipw = (const float*)d_in[13];
    const float* ipb = (const float*)d_in[14];
    const float* outw = (const float*)d_in[15];
    const float* outb = (const float*)d_in[16];
    float* out = (float*)d_out;

    int hasBoard = (out_size >= BATCH * (96 + 792)) ? 1 : 0;
    float* boardOut = out + (size_t)BATCH * 96;

    static const int kSmem = SMEM_FLOATS * 4;
    cudaFuncSetAttribute(k_fused, cudaFuncAttributeMaxDynamicSharedMemorySize, kSmem);
    k_fused<<<BATCH / 4, 256, kSmem>>>(t, ptab, w1, b1, w2, b2, w3, b3, lfc1, l1b,
                                       fcw, fcb, ipw, ipb, outw, outb,
                                       out, boardOut, hasBoard);
}